// round 6
// baseline (speedup 1.0000x reference)
#include <cuda_runtime.h>
#include <math.h>
#include <stdint.h>

typedef unsigned long long u64;

// ---------------- problem constants ----------------
// B=4, C=128, H=W=512, P=16, GH=GW=32, N=1024, PATCH_DIM=32768, DIM=512,
// MLP=256, DH=64, HEADS=(2,4,8), NUM_REL=3969

// ---------------- scratch (device globals) ----------------
__device__ __align__(16) float g_pw2[32768 * 512];   // permuted patch_w (64 MB)
__device__ __align__(16) float g_x[4096 * 512];      // residual stream
__device__ __align__(16) float g_xn[4096 * 512];     // LN output
__device__ __align__(16) float g_qkv[4096 * 1536];   // qkv (max inner=512)
__device__ __align__(16) float g_attn[33554432];     // scores, B*8*N*N (128 MB)
__device__ __align__(16) float g_o[4096 * 512];      // attention output
__device__ __align__(16) float g_h[4096 * 256];      // FFN hidden

#define BUF_X   0
#define BUF_XN  1
#define BUF_QKV 2
#define BUF_O   3
#define BUF_H   4
#define BUF_ATT 5
__device__ __forceinline__ float* buf(int id) {
    switch (id) {
        case BUF_X:   return g_x;
        case BUF_XN:  return g_xn;
        case BUF_QKV: return g_qkv;
        case BUF_O:   return g_o;
        case BUF_ATT: return g_attn;
        default:      return g_h;
    }
}

// ============================================================================
__global__ void k_zero(float* o, int n) {
    int i = blockIdx.x * blockDim.x + threadIdx.x;
    if (i < n) o[i] = 0.0f;
}

// ============================================================================
// permute patch_w rows:  in row (p1*16+p2)*128 + c  ->  out row c*256 + p1*16+p2
// ============================================================================
__global__ void k_permute_pw(const float* __restrict__ pw) {
    int idx = blockIdx.x * blockDim.x + threadIdx.x;
    if (idx >= 32768 * 128) return;
    int r  = idx >> 7;
    int d4 = idx & 127;
    int p  = r >> 7;
    int c  = r & 127;
    int rout = (c << 8) + p;
    float4 v = ((const float4*)pw)[(size_t)r * 128 + d4];
    ((float4*)g_pw2)[(size_t)rout * 128 + d4] = v;
}

// ============================================================================
// TF32 / ldmatrix helpers
// ============================================================================
__device__ __forceinline__ uint32_t f2tf(float f) {
    uint32_t r;
    asm("cvt.rna.tf32.f32 %0, %1;" : "=r"(r) : "f"(f));
    return r;
}
__device__ __forceinline__ float4 cvt4(float4 v) {
    v.x = __uint_as_float(f2tf(v.x));
    v.y = __uint_as_float(f2tf(v.y));
    v.z = __uint_as_float(f2tf(v.z));
    v.w = __uint_as_float(f2tf(v.w));
    return v;
}
__device__ __forceinline__ void mma8(float* c, const uint32_t* a,
                                     uint32_t b0, uint32_t b1) {
    asm("mma.sync.aligned.m16n8k8.row.col.f32.tf32.tf32.f32 "
        "{%0,%1,%2,%3},{%4,%5,%6,%7},{%8,%9},{%0,%1,%2,%3};"
        : "+f"(c[0]), "+f"(c[1]), "+f"(c[2]), "+f"(c[3])
        : "r"(a[0]), "r"(a[1]), "r"(a[2]), "r"(a[3]), "r"(b0), "r"(b1));
}
__device__ __forceinline__ void ldsm4(uint32_t& r0, uint32_t& r1,
                                      uint32_t& r2, uint32_t& r3, uint32_t a) {
    asm volatile("ldmatrix.sync.aligned.m8n8.x4.shared.b16 {%0,%1,%2,%3},[%4];"
                 : "=r"(r0), "=r"(r1), "=r"(r2), "=r"(r3) : "r"(a));
}
__device__ __forceinline__ uint32_t smem_u32(const void* p) {
    return (uint32_t)__cvta_generic_to_shared(p);
}
__device__ __forceinline__ uint32_t ldu(const float* p) {
    return __float_as_uint(*p);
}

// ============================================================================
// patch embed GEMM (TC, tf32, ldmatrix fragments):
//   g_x[m][d] = sum_k' A[m][k'] * pw2[k'][d] + pb[d] + pos[n][d]
// CTA 128x128, BK=32, 8 warps, double-buffered. A gathered from img.
// smem: both operands K-major [row][32 floats], granule swizz q^(row&7).
// ============================================================================
__global__ __launch_bounds__(256, 1)
void k_patch_tc(const float* __restrict__ img,
                const float* __restrict__ pb,
                const float* __restrict__ pos) {
    __shared__ __align__(16) float As[2][128 * 32];
    __shared__ __align__(16) float Bs[2][128 * 32];

    const int tid  = threadIdx.x;
    const int lane = tid & 31;
    const int wid  = tid >> 5;
    const int warp_m = (wid & 3) * 32;
    const int warp_n = (wid >> 2) * 64;
    const int m0 = blockIdx.y * 128;
    const int n0 = blockIdx.x * 128;

    // A gather: aq = k-quad (0..7), am = m-row (0..31, +32t)
    const int aq = tid & 7;
    const int am = tid >> 3;
    // B loader: bkg = k-group (0..7), bng = n-group (0..31)
    const int bkg = tid & 7;
    const int bng = tid >> 3;

    const float* abase[4];
#pragma unroll
    for (int t = 0; t < 4; t++) {
        int m_g = m0 + am + t * 32;
        int bb  = m_g >> 10;
        int tok = m_g & 1023;
        int gh = tok >> 5, gw = tok & 31;
        abase[t] = img + (size_t)bb * 33554432 + (size_t)(gh * 16) * 512 + gw * 16;
    }
    const float* bbase = g_pw2 + n0 + bng * 4;

    // byte store offsets
    uint32_t aSt[4], bSt[4];
#pragma unroll
    for (int t = 0; t < 4; t++) {
        int m = am + 32 * t;
        aSt[t] = m * 128 + ((aq ^ (m & 7)) << 4);
    }
#pragma unroll
    for (int s = 0; s < 4; s++) {
        int n = bng * 4 + s;
        bSt[s] = n * 128 + ((bkg ^ (n & 7)) << 4);
    }

    const uint32_t sA = smem_u32(As);
    const uint32_t sB = smem_u32(Bs);

    // fragment ldmatrix per-lane constants
    const int lane15 = lane & 15;
    const int hi = lane >> 4;
    uint32_t aFr[2]; int a7[2];
#pragma unroll
    for (int ma = 0; ma < 2; ma++) {
        int r = warp_m + 16 * ma + lane15;
        aFr[ma] = r * 128; a7[ma] = r & 7;
    }
    uint32_t bFr[4]; int b7[4];
#pragma unroll
    for (int np = 0; np < 4; np++) {
        int n = warp_n + 16 * np + lane15;
        bFr[np] = n * 128; b7[np] = n & 7;
    }

    float c[2][8][4];
#pragma unroll
    for (int i = 0; i < 2; i++)
#pragma unroll
        for (int j = 0; j < 8; j++)
#pragma unroll
            for (int q = 0; q < 4; q++) c[i][j][q] = 0.0f;

    float4 pa[4], rb[4];

    // ---- prologue (k0 = 0) ----
    {
        int k = aq * 4;
        int cc = k >> 8, rem = k & 255;
        const size_t aoff = (size_t)cc * 262144 + (rem >> 4) * 512 + (rem & 15);
#pragma unroll
        for (int t = 0; t < 4; t++) pa[t] = *(const float4*)(abase[t] + aoff);
#pragma unroll
        for (int i = 0; i < 4; i++)
            rb[i] = *(const float4*)(bbase + (size_t)(bkg * 4 + i) * 512);
#pragma unroll
        for (int t = 0; t < 4; t++)
            *(float4*)((char*)As[0] + aSt[t]) = cvt4(pa[t]);
        *(float4*)((char*)Bs[0] + bSt[0]) = cvt4(make_float4(rb[0].x, rb[1].x, rb[2].x, rb[3].x));
        *(float4*)((char*)Bs[0] + bSt[1]) = cvt4(make_float4(rb[0].y, rb[1].y, rb[2].y, rb[3].y));
        *(float4*)((char*)Bs[0] + bSt[2]) = cvt4(make_float4(rb[0].z, rb[1].z, rb[2].z, rb[3].z));
        *(float4*)((char*)Bs[0] + bSt[3]) = cvt4(make_float4(rb[0].w, rb[1].w, rb[2].w, rb[3].w));
    }
    __syncthreads();

    int bsel = 0;
    for (int it = 0; it < 1024; it++) {
        if (it < 1023) {
            int k0 = (it + 1) * 32;
            int k = k0 + aq * 4;
            int cc = k >> 8, rem = k & 255;
            const size_t aoff = (size_t)cc * 262144 + (rem >> 4) * 512 + (rem & 15);
#pragma unroll
            for (int t = 0; t < 4; t++) pa[t] = *(const float4*)(abase[t] + aoff);
#pragma unroll
            for (int i = 0; i < 4; i++)
                rb[i] = *(const float4*)(bbase + (size_t)(k0 + bkg * 4 + i) * 512);
        }

        const uint32_t aB = sA + (bsel << 14);
        const uint32_t bB = sB + (bsel << 14);
#pragma unroll
        for (int kk = 0; kk < 4; kk++) {
            uint32_t af[2][4];
#pragma unroll
            for (int ma = 0; ma < 2; ma++)
                ldsm4(af[ma][0], af[ma][1], af[ma][2], af[ma][3],
                      aB + aFr[ma] + (uint32_t)((((2 * kk + hi) ^ a7[ma])) << 4));
#pragma unroll
            for (int np = 0; np < 4; np++) {
                uint32_t b0, b1, b2, b3;
                ldsm4(b0, b1, b2, b3,
                      bB + bFr[np] + (uint32_t)((((2 * kk + hi) ^ b7[np])) << 4));
#pragma unroll
                for (int ma = 0; ma < 2; ma++) {
                    mma8(c[ma][2 * np],     af[ma], b0, b2);
                    mma8(c[ma][2 * np + 1], af[ma], b1, b3);
                }
            }
        }

        if (it < 1023) {
            int nb = bsel ^ 1;
#pragma unroll
            for (int t = 0; t < 4; t++)
                *(float4*)((char*)As[nb] + aSt[t]) = cvt4(pa[t]);
            *(float4*)((char*)Bs[nb] + bSt[0]) = cvt4(make_float4(rb[0].x, rb[1].x, rb[2].x, rb[3].x));
            *(float4*)((char*)Bs[nb] + bSt[1]) = cvt4(make_float4(rb[0].y, rb[1].y, rb[2].y, rb[3].y));
            *(float4*)((char*)Bs[nb] + bSt[2]) = cvt4(make_float4(rb[0].z, rb[1].z, rb[2].z, rb[3].z));
            *(float4*)((char*)Bs[nb] + bSt[3]) = cvt4(make_float4(rb[0].w, rb[1].w, rb[2].w, rb[3].w));
            __syncthreads();
            bsel = nb;
        }
    }

    // ---- epilogue: + patch_b + pos_emb ----
#pragma unroll
    for (int ma = 0; ma < 2; ma++) {
        int r0 = m0 + warp_m + ma * 16 + (lane >> 2);
        int r1 = r0 + 8;
        int tok0 = r0 & 1023, tok1 = r1 & 1023;
#pragma unroll
        for (int na = 0; na < 8; na++) {
            int col = n0 + warp_n + na * 8 + (lane & 3) * 2;
            float2 o0, o1;
            o0.x = c[ma][na][0] + pb[col]     + pos[(size_t)tok0 * 512 + col];
            o0.y = c[ma][na][1] + pb[col + 1] + pos[(size_t)tok0 * 512 + col + 1];
            o1.x = c[ma][na][2] + pb[col]     + pos[(size_t)tok1 * 512 + col];
            o1.y = c[ma][na][3] + pb[col + 1] + pos[(size_t)tok1 * 512 + col + 1];
            *(float2*)(g_x + (size_t)r0 * 512 + col) = o0;
            *(float2*)(g_x + (size_t)r1 * 512 + col) = o1;
        }
    }
}

// ============================================================================
// generic TC GEMM (tf32, ldmatrix):  C = A @ B (+bias)(+gelu)(+resid g_x)
// CTA 128 x BN, BK=32, 8 warps, double-buffered, batched via blockIdx.z.
// ============================================================================
template<int BN>
__global__ __launch_bounds__(256, 1)
void k_tc_nn(int aId, u64 aBatch, u64 aHead, int ldA,
             const float* __restrict__ Bext, int bId,
             u64 bBatch, u64 bHead, u64 bOff, int ldB,
             int cId, u64 cBatch, u64 cHead, u64 cOff, int ldC,
             int K, int hc,
             const float* __restrict__ bias, int addResid, int gelu) {
    constexpr int NA = BN / 16;          // n atoms per warp
    constexpr int NP = BN / 32;          // ldsm n-pairs per warp
    constexpr int BBY = BN * 128;        // B buffer bytes

    __shared__ __align__(16) float As[2][128 * 32];
    __shared__ __align__(16) float Bs[2][BN * 32];

    const int tid  = threadIdx.x;
    const int lane = tid & 31;
    const int wid  = tid >> 5;
    const int warp_m = (wid & 3) * 32;
    const int warp_n = (wid >> 2) * (BN / 2);
    const int m0 = blockIdx.y * 128;
    const int n0 = blockIdx.x * BN;

    const int z  = blockIdx.z;
    const int bb = z / hc;
    const int hd = z % hc;
    const float* A = buf(aId) + (size_t)bb * aBatch + (size_t)hd * aHead;
    const float* Bg = (bId < 0 ? Bext : buf(bId)) +
                      (size_t)bb * bBatch + (size_t)hd * bHead + bOff;
    float* C = buf(cId) + (size_t)bb * cBatch + (size_t)hd * cHead + cOff;

    const int aq = tid & 7;
    const int am = tid >> 3;
    const int bkg = tid & 7;
    const int bng = tid >> 3;
    const bool bAct = (bng < BN / 4);

    uint32_t aSt[4], bSt[4];
#pragma unroll
    for (int t = 0; t < 4; t++) {
        int m = am + 32 * t;
        aSt[t] = m * 128 + ((aq ^ (m & 7)) << 4);
    }
#pragma unroll
    for (int s = 0; s < 4; s++) {
        int n = bng * 4 + s;
        bSt[s] = n * 128 + ((bkg ^ (n & 7)) << 4);
    }

    const uint32_t sA = smem_u32(As);
    const uint32_t sB = smem_u32(Bs);

    const int lane15 = lane & 15;
    const int hi = lane >> 4;
    uint32_t aFr[2]; int a7[2];
#pragma unroll
    for (int ma = 0; ma < 2; ma++) {
        int r = warp_m + 16 * ma + lane15;
        aFr[ma] = r * 128; a7[ma] = r & 7;
    }
    uint32_t bFr[NP]; int b7[NP];
#pragma unroll
    for (int np = 0; np < NP; np++) {
        int n = warp_n + 16 * np + lane15;
        bFr[np] = n * 128; b7[np] = n & 7;
    }

    float c[2][NA][4];
#pragma unroll
    for (int i = 0; i < 2; i++)
#pragma unroll
        for (int j = 0; j < NA; j++)
#pragma unroll
            for (int q = 0; q < 4; q++) c[i][j][q] = 0.0f;

    float4 pa[4], rb[4];

    // prologue
    {
#pragma unroll
        for (int t = 0; t < 4; t++)
            pa[t] = *(const float4*)(A + (size_t)(m0 + am + t * 32) * ldA + aq * 4);
        if (bAct) {
#pragma unroll
            for (int i = 0; i < 4; i++)
                rb[i] = *(const float4*)(Bg + (size_t)(bkg * 4 + i) * ldB + n0 + bng * 4);
        }
#pragma unroll
        for (int t = 0; t < 4; t++)
            *(float4*)((char*)As[0] + aSt[t]) = cvt4(pa[t]);
        if (bAct) {
            *(float4*)((char*)Bs[0] + bSt[0]) = cvt4(make_float4(rb[0].x, rb[1].x, rb[2].x, rb[3].x));
            *(float4*)((char*)Bs[0] + bSt[1]) = cvt4(make_float4(rb[0].y, rb[1].y, rb[2].y, rb[3].y));
            *(float4*)((char*)Bs[0] + bSt[2]) = cvt4(make_float4(rb[0].z, rb[1].z, rb[2].z, rb[3].z));
            *(float4*)((char*)Bs[0] + bSt[3]) = cvt4(make_float4(rb[0].w, rb[1].w, rb[2].w, rb[3].w));
        }
    }
    __syncthreads();

    const int iters = K >> 5;
    int bsel = 0;
    for (int it = 0; it < iters; it++) {
        if (it < iters - 1) {
            int k0 = (it + 1) * 32;
#pragma unroll
            for (int t = 0; t < 4; t++)
                pa[t] = *(const float4*)(A + (size_t)(m0 + am + t * 32) * ldA + k0 + aq * 4);
            if (bAct) {
#pragma unroll
                for (int i = 0; i < 4; i++)
                    rb[i] = *(const float4*)(Bg + (size_t)(k0 + bkg * 4 + i) * ldB + n0 + bng * 4);
            }
        }

        const uint32_t aB = sA + (bsel << 14);
        const uint32_t bB = sB + (uint32_t)bsel * BBY;
#pragma unroll
        for (int kk = 0; kk < 4; kk++) {
            uint32_t af[2][4];
#pragma unroll
            for (int ma = 0; ma < 2; ma++)
                ldsm4(af[ma][0], af[ma][1], af[ma][2], af[ma][3],
                      aB + aFr[ma] + (uint32_t)((((2 * kk + hi) ^ a7[ma])) << 4));
#pragma unroll
            for (int np = 0; np < NP; np++) {
                uint32_t b0, b1, b2, b3;
                ldsm4(b0, b1, b2, b3,
                      bB + bFr[np] + (uint32_t)((((2 * kk + hi) ^ b7[np])) << 4));
#pragma unroll
                for (int ma = 0; ma < 2; ma++) {
                    mma8(c[ma][2 * np],     af[ma], b0, b2);
                    mma8(c[ma][2 * np + 1], af[ma], b1, b3);
                }
            }
        }

        if (it < iters - 1) {
            int nb = bsel ^ 1;
#pragma unroll
            for (int t = 0; t < 4; t++)
                *(float4*)((char*)As[nb] + aSt[t]) = cvt4(pa[t]);
            if (bAct) {
                *(float4*)((char*)Bs[nb] + bSt[0]) = cvt4(make_float4(rb[0].x, rb[1].x, rb[2].x, rb[3].x));
                *(float4*)((char*)Bs[nb] + bSt[1]) = cvt4(make_float4(rb[0].y, rb[1].y, rb[2].y, rb[3].y));
                *(float4*)((char*)Bs[nb] + bSt[2]) = cvt4(make_float4(rb[0].z, rb[1].z, rb[2].z, rb[3].z));
                *(float4*)((char*)Bs[nb] + bSt[3]) = cvt4(make_float4(rb[0].w, rb[1].w, rb[2].w, rb[3].w));
            }
            __syncthreads();
            bsel = nb;
        }
    }

    // epilogue
#pragma unroll
    for (int ma = 0; ma < 2; ma++) {
        int r0 = m0 + warp_m + ma * 16 + (lane >> 2);
        int r1 = r0 + 8;
#pragma unroll
        for (int na = 0; na < NA; na++) {
            int col = n0 + warp_n + na * 8 + (lane & 3) * 2;
            float v[4] = {c[ma][na][0], c[ma][na][1], c[ma][na][2], c[ma][na][3]};
            if (bias) {
                float b0 = bias[col], b1 = bias[col + 1];
                v[0] += b0; v[1] += b1; v[2] += b0; v[3] += b1;
            }
            if (gelu) {
#pragma unroll
                for (int q = 0; q < 4; q++)
                    v[q] = 0.5f * v[q] * (1.0f + erff(v[q] * 0.70710678118654752f));
            }
            if (addResid) {
                v[0] += g_x[(size_t)r0 * 512 + col];
                v[1] += g_x[(size_t)r0 * 512 + col + 1];
                v[2] += g_x[(size_t)r1 * 512 + col];
                v[3] += g_x[(size_t)r1 * 512 + col + 1];
            }
            *(float2*)(C + (size_t)r0 * ldC + col) = make_float2(v[0], v[1]);
            *(float2*)(C + (size_t)r1 * ldC + col) = make_float2(v[2], v[3]);
        }
    }
}

// ============================================================================
// attention scores (TC, TF32, K=64 single shot) — unchanged (validated R5)
// ============================================================================
__global__ __launch_bounds__(256, 1)
void k_tc_scores(const float* __restrict__ tbl, int qkvld, int inner, int hc) {
    __shared__ __align__(16) float As[128 * 64];
    __shared__ __align__(16) float Bs[64 * 136];

    const int tid  = threadIdx.x;
    const int lane = tid & 31;
    const int wid  = tid >> 5;
    const int warp_m = (wid & 3) * 32;
    const int warp_n = (wid >> 2) * 64;
    const int i0 = blockIdx.y * 128;
    const int j0 = blockIdx.x * 128;

    const int z = blockIdx.z;
    const int bb = z / hc, head = z % hc;
    const float* Qb = g_qkv + (size_t)bb * 1024 * qkvld + head * 64;
    const float* Kb = Qb + inner;

    {
        const int aq = tid & 15;
        const int am = tid >> 4;
#pragma unroll
        for (int t = 0; t < 8; t++) {
            int m = am + t * 16;
            float4 v = *(const float4*)(Qb + (size_t)(i0 + m) * qkvld + aq * 4);
            int p = (aq & 8) | ((aq ^ (m & 7)) & 7);
            *(float4*)&As[m * 64 + (p << 2)] = cvt4(v);
        }
    }
    {
        const int n = tid & 127;
        const int cc = tid >> 7;
#pragma unroll
        for (int t = 0; t < 8; t++) {
            int kq = cc + t * 2;
            float4 v = cvt4(*(const float4*)(Kb + (size_t)(j0 + n) * qkvld + kq * 4));
            Bs[(kq * 4 + 0) * 136 + n] = v.x;
            Bs[(kq * 4 + 1) * 136 + n] = v.y;
            Bs[(kq * 4 + 2) * 136 + n] = v.z;
            Bs[(kq * 4 + 3) * 136 + n] = v.w;
        }
    }
    __syncthreads();

    float c[2][8][4];
#pragma unroll
    for (int i = 0; i < 2; i++)
#pragma unroll
        for (int j = 0; j < 8; j++)
#pragma unroll
            for (int q = 0; q < 4; q++) c[i][j][q] = 0.0f;

#pragma unroll
    for (int kk = 0; kk < 8; kk++) {
        uint32_t af[2][4], bf[8][2];
        const int kq0 = kk * 2, kq1 = kk * 2 + 1;
        const int kb  = lane & 3;
#pragma unroll
        for (int ma = 0; ma < 2; ma++) {
            int r0 = warp_m + ma * 16 + (lane >> 2);
            int r1 = r0 + 8;
            int p00 = (kq0 & 8) | ((kq0 ^ (r0 & 7)) & 7);
            int p01 = (kq0 & 8) | ((kq0 ^ (r1 & 7)) & 7);
            int p10 = (kq1 & 8) | ((kq1 ^ (r0 & 7)) & 7);
            int p11 = (kq1 & 8) | ((kq1 ^ (r1 & 7)) & 7);
            af[ma][0] = ldu(&As[r0 * 64 + (p00 << 2) + kb]);
            af[ma][1] = ldu(&As[r1 * 64 + (p01 << 2) + kb]);
            af[ma][2] = ldu(&As[r0 * 64 + (p10 << 2) + kb]);
            af[ma][3] = ldu(&As[r1 * 64 + (p11 << 2) + kb]);
        }
#pragma unroll
        for (int na = 0; na < 8; na++) {
            int n = warp_n + na * 8 + (lane >> 2);
            bf[na][0] = ldu(&Bs[(kk * 8 + kb) * 136 + n]);
            bf[na][1] = ldu(&Bs[(kk * 8 + 4 + kb) * 136 + n]);
        }
#pragma unroll
        for (int ma = 0; ma < 2; ma++)
#pragma unroll
            for (int na = 0; na < 8; na++)
                mma8(c[ma][na], af[ma], bf[na][0], bf[na][1]);
    }

    float* Sp = g_attn + (size_t)z * 1048576;
#pragma unroll
    for (int ma = 0; ma < 2; ma++) {
        int r0 = i0 + warp_m + ma * 16 + (lane >> 2);
        int r1 = r0 + 8;
        int ih0 = r0 >> 5, iw0 = r0 & 31;
        int ih1 = r1 >> 5, iw1 = r1 & 31;
#pragma unroll
        for (int na = 0; na < 8; na++) {
            int jj = j0 + warp_n + na * 8 + (lane & 3) * 2;
            int jh0 = jj >> 5, jw0 = jj & 31;
            int jh1 = (jj + 1) >> 5, jw1 = (jj + 1) & 31;
            float2 o0, o1;
            o0.x = c[ma][na][0] * 0.125f +
                   tbl[(size_t)((ih0 - jh0 + 31) * 63 + (iw0 - jw0 + 31)) * hc + head];
            o0.y = c[ma][na][1] * 0.125f +
                   tbl[(size_t)((ih0 - jh1 + 31) * 63 + (iw0 - jw1 + 31)) * hc + head];
            o1.x = c[ma][na][2] * 0.125f +
                   tbl[(size_t)((ih1 - jh0 + 31) * 63 + (iw1 - jw0 + 31)) * hc + head];
            o1.y = c[ma][na][3] * 0.125f +
                   tbl[(size_t)((ih1 - jh1 + 31) * 63 + (iw1 - jw1 + 31)) * hc + head];
            *(float2*)(Sp + (size_t)r0 * 1024 + jj) = o0;
            *(float2*)(Sp + (size_t)r1 * 1024 + jj) = o1;
        }
    }
}

// ============================================================================
// row softmax over 1024 columns
// ============================================================================
__global__ void k_softmax() {
    __shared__ float sh[8];
    int tid = threadIdx.x;
    float* row = g_attn + (size_t)blockIdx.x * 1024;
    float4 v = ((float4*)row)[tid];
    float m = fmaxf(fmaxf(v.x, v.y), fmaxf(v.z, v.w));
#pragma unroll
    for (int o = 16; o; o >>= 1) m = fmaxf(m, __shfl_xor_sync(0xffffffffu, m, o));
    if ((tid & 31) == 0) sh[tid >> 5] = m;
    __syncthreads();
    float m8 = sh[0];
#pragma unroll
    for (int i = 1; i < 8; i++) m8 = fmaxf(m8, sh[i]);
    float4 e;
    e.x = __expf(v.x - m8); e.y = __expf(v.y - m8);
    e.z = __expf(v.z - m8); e.w = __expf(v.w - m8);
    float s = e.x + e.y + e.z + e.w;
#pragma unroll
    for (int o = 16; o; o >>= 1) s += __shfl_xor_sync(0xffffffffu, s, o);
    __syncthreads();
    if ((tid & 31) == 0) sh[tid >> 5] = s;
    __syncthreads();
    float tot = 0.f;
#pragma unroll
    for (int i = 0; i < 8; i++) tot += sh[i];
    float inv = 1.0f / tot;
    e.x *= inv; e.y *= inv; e.z *= inv; e.w *= inv;
    ((float4*)row)[tid] = e;
}

// ============================================================================
// LayerNorm over 512
// ============================================================================
__global__ void k_layernorm(const float* __restrict__ s, const float* __restrict__ b) {
    __shared__ float ssum[4], ssq[4];
    int tid = threadIdx.x;
    int row = blockIdx.x;
    float4 v = ((const float4*)(g_x + (size_t)row * 512))[tid];
    float sum = v.x + v.y + v.z + v.w;
    float sq  = v.x * v.x + v.y * v.y + v.z * v.z + v.w * v.w;
#pragma unroll
    for (int o = 16; o; o >>= 1) {
        sum += __shfl_xor_sync(0xffffffffu, sum, o);
        sq  += __shfl_xor_sync(0xffffffffu, sq, o);
    }
    if ((tid & 31) == 0) { ssum[tid >> 5] = sum; ssq[tid >> 5] = sq; }
    __syncthreads();
    float ts = ssum[0] + ssum[1] + ssum[2] + ssum[3];
    float tq = ssq[0] + ssq[1] + ssq[2] + ssq[3];
    float mean = ts * (1.0f / 512.0f);
    float var  = tq * (1.0f / 512.0f) - mean * mean;
    float rstd = rsqrtf(var + 1e-5f);
    int d = tid << 2;
    float4 sv = *(const float4*)(s + d);
    float4 bv = *(const float4*)(b + d);
    float4 o;
    o.x = (v.x - mean) * rstd * sv.x + bv.x;
    o.y = (v.y - mean) * rstd * sv.y + bv.y;
    o.z = (v.z - mean) * rstd * sv.z + bv.z;
    o.w = (v.w - mean) * rstd * sv.w + bv.w;
    ((float4*)(g_xn + (size_t)row * 512))[tid] = o;
}

// ============================================================================
// final layout: out[b][d][n] = g_x[b][n][d]
// ============================================================================
__global__ void k_out(float* __restrict__ out) {
    __shared__ float t[32][33];
    int bb = blockIdx.z;
    int n0 = blockIdx.x * 32, d0 = blockIdx.y * 32;
    int tx = threadIdx.x, ty = threadIdx.y;
#pragma unroll
    for (int i = 0; i < 32; i += 8)
        t[ty + i][tx] = g_x[((size_t)bb * 1024 + n0 + ty + i) * 512 + d0 + tx];
    __syncthreads();
#pragma unroll
    for (int i = 0; i < 32; i += 8)
        out[((size_t)bb * 512 + d0 + ty + i) * 1024 + n0 + tx] = t[tx][ty + i];
}

// ============================================================================
// host orchestration
// ============================================================================
extern "C" void kernel_launch(void* const* d_in, const int* in_sizes, int n_in,
                              void* d_out, int out_size) {
    const float *img = 0, *patch_w = 0, *patch_b = 0, *pos_emb = 0;
    const float *ln1_s = 0, *ln1_b = 0, *ln2_s = 0, *ln2_b = 0;
    const float *qkv_w[3] = {0, 0, 0}, *out_w[3] = {0, 0, 0}, *out_b[3] = {0, 0, 0};
    const float *tbl[3] = {0, 0, 0};
    const float *ff_w1 = 0, *ff_b1 = 0, *ff_w2 = 0, *ff_b2 = 0;
    int c512 = 0, c1536 = 0, c393 = 0;
    for (int i = 0; i < n_in; i++) {
        const float* p = (const float*)d_in[i];
        switch (in_sizes[i]) {
            case 134217728: img = p; break;
            case 16777216: patch_w = p; break;
            case 524288:   pos_emb = p; break;
            case 512: {
                const float** t[4] = {&patch_b, &out_b[0], &out_b[1], &out_b[2]};
                if (c512 < 4) *t[c512] = p;
                c512++;
            } break;
            case 1536: {
                const float** t[5] = {&ln1_s, &ln1_b, &ln2_s, &ln2_b, &ff_b2};
                if (c1536 < 5) *t[c1536] = p;
                c1536++;
            } break;
            case 768:    ff_b1 = p; break;
            case 196608: qkv_w[0] = p; break;
            case 393216: {
                const float** t[3] = {&qkv_w[1], &ff_w1, &ff_w2};
                if (c393 < 3) *t[c393] = p;
                c393++;
            } break;
            case 786432: qkv_w[2] = p; break;
            case 65536:  out_w[0] = p; break;
            case 131072: out_w[1] = p; break;
            case 262144: out_w[2] = p; break;
            case 7938:   tbl[0] = p; break;
            case 15876:  tbl[1] = p; break;
            case 31752:  tbl[2] = p; break;
            default: break;
        }
    }

    bool ok = img && patch_w && patch_b && pos_emb && ln1_s && ln1_b && ln2_s &&
              ln2_b && ff_w1 && ff_b1 && ff_w2 && ff_b2;
    for (int l = 0; l < 3; l++)
        ok = ok && qkv_w[l] && out_w[l] && out_b[l] && tbl[l];
    if (!ok) {
        k_zero<<<(out_size + 255) / 256, 256>>>((float*)d_out, out_size);
        return;
    }

    k_permute_pw<<<(32768 * 128 + 255) / 256, 256>>>(patch_w);
    k_patch_tc<<<dim3(4, 32), 256>>>(img, patch_b, pos_emb);

    const int heads[3] = {2, 4, 8};
    for (int l = 0; l < 3; l++) {
        int h = heads[l];
        int inner = 64 * h;
        int qkvld = 3 * inner;

        // ---- attention ----
        k_layernorm<<<4096, 128>>>(ln1_s + l * 512, ln1_b + l * 512);
        k_tc_nn<128><<<dim3(qkvld / 128, 32, 1), 256>>>(
            BUF_XN, 0ULL, 0ULL, 512,
            qkv_w[l], -1, 0ULL, 0ULL, 0ULL, qkvld,
            BUF_QKV, 0ULL, 0ULL, 0ULL, qkvld,
            512, 1, nullptr, 0, 0);
        k_tc_scores<<<dim3(8, 8, 4 * h), 256>>>(tbl[l], qkvld, inner, h);
        k_softmax<<<4 * h * 1024, 256>>>();
        k_tc_nn<64><<<dim3(1, 8, 4 * h), 256>>>(
            BUF_ATT, (u64)h * 1048576ULL, 1048576ULL, 1024,
            nullptr, BUF_QKV, (u64)1024 * qkvld, 64ULL,
            (u64)(2 * inner), qkvld,
            BUF_O, (u64)1024 * inner, 64ULL, 0ULL, inner,
            1024, h, nullptr, 0, 0);
        k_tc_nn<128><<<dim3(4, 32, 1), 256>>>(
            BUF_O, 0ULL, 0ULL, inner,
            out_w[l], -1, 0ULL, 0ULL, 0ULL, 512,
            BUF_X, 0ULL, 0ULL, 0ULL, 512,
            inner, 1, out_b[l], 1, 0);

        // ---- feed-forward ----
        k_layernorm<<<4096, 128>>>(ln2_s + l * 512, ln2_b + l * 512);
        k_tc_nn<128><<<dim3(2, 32, 1), 256>>>(
            BUF_XN, 0ULL, 0ULL, 512,
            ff_w1 + (size_t)l * 512 * 256, -1, 0ULL, 0ULL, 0ULL, 256,
            BUF_H, 0ULL, 0ULL, 0ULL, 256,
            512, 1, ff_b1 + l * 256, 0, 1);
        k_tc_nn<128><<<dim3(4, 32, 1), 256>>>(
            BUF_H, 0ULL, 0ULL, 256,
            ff_w2 + (size_t)l * 256 * 512, -1, 0ULL, 0ULL, 0ULL, 512,
            BUF_X, 0ULL, 0ULL, 0ULL, 512,
            256, 1, ff_b2 + l * 512, 1, 0);
    }

    k_out<<<dim3(32, 16, 4), dim3(32, 8)>>>((float*)d_out);
}

// round 7
// speedup vs baseline: 1.3101x; 1.3101x over previous
#include <cuda_runtime.h>
#include <math.h>
#include <stdint.h>

typedef unsigned long long u64;

// ---------------- problem constants ----------------
// B=4, C=128, H=W=512, P=16, GH=GW=32, N=1024, PATCH_DIM=32768, DIM=512,
// MLP=256, DH=64, HEADS=(2,4,8), NUM_REL=3969

// ---------------- scratch (device globals) ----------------
__device__ __align__(16) float g_pw2[32768 * 512];   // permuted patch_w (64 MB)
__device__ __align__(16) float g_x[4096 * 512];      // residual stream
__device__ __align__(16) float g_xn[4096 * 512];     // LN output
__device__ __align__(16) float g_qkv[4096 * 1536];   // qkv (max inner=512)
__device__ __align__(16) float g_attn[33554432];     // scores, B*8*N*N (128 MB)
__device__ __align__(16) float g_o[4096 * 512];      // attention output
__device__ __align__(16) float g_h[4096 * 256];      // FFN hidden

#define BUF_X   0
#define BUF_XN  1
#define BUF_QKV 2
#define BUF_O   3
#define BUF_H   4
#define BUF_ATT 5
__device__ __forceinline__ float* buf(int id) {
    switch (id) {
        case BUF_X:   return g_x;
        case BUF_XN:  return g_xn;
        case BUF_QKV: return g_qkv;
        case BUF_O:   return g_o;
        case BUF_ATT: return g_attn;
        default:      return g_h;
    }
}

// ============================================================================
__global__ void k_zero(float* o, int n) {
    int i = blockIdx.x * blockDim.x + threadIdx.x;
    if (i < n) o[i] = 0.0f;
}

// ============================================================================
// permute patch_w rows:  in row (p1*16+p2)*128 + c  ->  out row c*256 + p1*16+p2
// ============================================================================
__global__ void k_permute_pw(const float* __restrict__ pw) {
    int idx = blockIdx.x * blockDim.x + threadIdx.x;
    if (idx >= 32768 * 128) return;
    int r  = idx >> 7;
    int d4 = idx & 127;
    int p  = r >> 7;
    int c  = r & 127;
    int rout = (c << 8) + p;
    float4 v = ((const float4*)pw)[(size_t)r * 128 + d4];
    ((float4*)g_pw2)[(size_t)rout * 128 + d4] = v;
}

// ============================================================================
// TF32 helpers
// ============================================================================
__device__ __forceinline__ uint32_t f2tf(float f) {
    uint32_t r;
    asm("cvt.rna.tf32.f32 %0, %1;" : "=r"(r) : "f"(f));
    return r;
}
__device__ __forceinline__ float4 cvt4(float4 v) {
    v.x = __uint_as_float(f2tf(v.x));
    v.y = __uint_as_float(f2tf(v.y));
    v.z = __uint_as_float(f2tf(v.z));
    v.w = __uint_as_float(f2tf(v.w));
    return v;
}
__device__ __forceinline__ void mma8(float* c, const uint32_t* a,
                                     uint32_t b0, uint32_t b1) {
    asm("mma.sync.aligned.m16n8k8.row.col.f32.tf32.tf32.f32 "
        "{%0,%1,%2,%3},{%4,%5,%6,%7},{%8,%9},{%0,%1,%2,%3};"
        : "+f"(c[0]), "+f"(c[1]), "+f"(c[2]), "+f"(c[3])
        : "r"(a[0]), "r"(a[1]), "r"(a[2]), "r"(a[3]), "r"(b0), "r"(b1));
}
__device__ __forceinline__ uint32_t ldu(const float* p) {
    return __float_as_uint(*p);
}

// ============================================================================
// patch embed GEMM (TC, tf32): 512 threads, 16 warps (warp tile 32x32),
// CTA 128x128, BK=32, double-buffered. A gathered from img.
// ============================================================================
__global__ __launch_bounds__(512, 1)
void k_patch_tc(const float* __restrict__ img,
                const float* __restrict__ pb,
                const float* __restrict__ pos) {
    __shared__ __align__(16) float As[2][128 * 32];
    __shared__ __align__(16) float Bs[2][32 * 136];

    const int tid  = threadIdx.x;
    const int lane = tid & 31;
    const int wid  = tid >> 5;             // 0..15
    const int warp_m = (wid & 3) * 32;
    const int warp_n = (wid >> 2) * 32;
    const int m0 = blockIdx.y * 128;
    const int n0 = blockIdx.x * 128;

    const int aq = tid & 7;                // k-quad
    const int am = tid >> 3;               // 0..63, rows am / am+64
    const int bc = tid & 31;               // n float4-chunk
    const int bk = tid >> 5;               // 0..15, rows bk / bk+16

    const float* abase[2];
#pragma unroll
    for (int t = 0; t < 2; t++) {
        int m_g = m0 + am + t * 64;
        int bb  = m_g >> 10;
        int tok = m_g & 1023;
        int gh = tok >> 5, gw = tok & 31;
        abase[t] = img + (size_t)bb * 33554432 + (size_t)(gh * 16) * 512 + gw * 16;
    }
    const float* bbase = g_pw2 + n0 + bc * 4;

    const int aw = am * 32 + ((aq ^ (am & 7)) << 2);   // (am+64)&7 == am&7
    const int bw = bk * 136 + bc * 4;

    float c[2][4][4];
#pragma unroll
    for (int i = 0; i < 2; i++)
#pragma unroll
        for (int j = 0; j < 4; j++)
#pragma unroll
            for (int q = 0; q < 4; q++) c[i][j][q] = 0.0f;

    float4 pa[2], pv[2];

    // ---- prologue (k0 = 0) ----
    {
        int k = aq * 4;
        int cc = k >> 8, rem = k & 255;
        const size_t aoff = (size_t)cc * 262144 + (rem >> 4) * 512 + (rem & 15);
#pragma unroll
        for (int t = 0; t < 2; t++) pa[t] = *(const float4*)(abase[t] + aoff);
#pragma unroll
        for (int t = 0; t < 2; t++)
            pv[t] = *(const float4*)(bbase + (size_t)(bk + t * 16) * 512);
#pragma unroll
        for (int t = 0; t < 2; t++) *(float4*)&As[0][aw + t * 2048] = cvt4(pa[t]);
#pragma unroll
        for (int t = 0; t < 2; t++) *(float4*)&Bs[0][bw + t * 16 * 136] = cvt4(pv[t]);
    }
    __syncthreads();

    int bsel = 0;
    for (int it = 0; it < 1024; it++) {
        if (it < 1023) {
            int k0 = (it + 1) * 32;
            int k = k0 + aq * 4;
            int cc = k >> 8, rem = k & 255;
            const size_t aoff = (size_t)cc * 262144 + (rem >> 4) * 512 + (rem & 15);
#pragma unroll
            for (int t = 0; t < 2; t++) pa[t] = *(const float4*)(abase[t] + aoff);
#pragma unroll
            for (int t = 0; t < 2; t++)
                pv[t] = *(const float4*)(bbase + (size_t)(k0 + bk + t * 16) * 512);
        }

        const float* Asb = As[bsel];
        const float* Bsb = Bs[bsel];
#pragma unroll
        for (int kk = 0; kk < 4; kk++) {
            uint32_t af[2][4], bf[4][2];
            const int kq0 = kk * 2, kq1 = kk * 2 + 1;
            const int kb  = lane & 3;
#pragma unroll
            for (int ma = 0; ma < 2; ma++) {
                int r0 = warp_m + ma * 16 + (lane >> 2);
                int r1 = r0 + 8;
                af[ma][0] = ldu(&Asb[r0 * 32 + ((kq0 ^ (r0 & 7)) << 2) + kb]);
                af[ma][1] = ldu(&Asb[r1 * 32 + ((kq0 ^ (r1 & 7)) << 2) + kb]);
                af[ma][2] = ldu(&Asb[r0 * 32 + ((kq1 ^ (r0 & 7)) << 2) + kb]);
                af[ma][3] = ldu(&Asb[r1 * 32 + ((kq1 ^ (r1 & 7)) << 2) + kb]);
            }
#pragma unroll
            for (int na = 0; na < 4; na++) {
                int n = warp_n + na * 8 + (lane >> 2);
                bf[na][0] = ldu(&Bsb[(kk * 8 + kb) * 136 + n]);
                bf[na][1] = ldu(&Bsb[(kk * 8 + 4 + kb) * 136 + n]);
            }
#pragma unroll
            for (int ma = 0; ma < 2; ma++)
#pragma unroll
                for (int na = 0; na < 4; na++)
                    mma8(c[ma][na], af[ma], bf[na][0], bf[na][1]);
        }

        if (it < 1023) {
            int nb = bsel ^ 1;
#pragma unroll
            for (int t = 0; t < 2; t++) *(float4*)&As[nb][aw + t * 2048] = cvt4(pa[t]);
#pragma unroll
            for (int t = 0; t < 2; t++) *(float4*)&Bs[nb][bw + t * 16 * 136] = cvt4(pv[t]);
            __syncthreads();
            bsel = nb;
        }
    }

    // ---- epilogue: + patch_b + pos_emb ----
#pragma unroll
    for (int ma = 0; ma < 2; ma++) {
        int r0 = m0 + warp_m + ma * 16 + (lane >> 2);
        int r1 = r0 + 8;
        int tok0 = r0 & 1023, tok1 = r1 & 1023;
#pragma unroll
        for (int na = 0; na < 4; na++) {
            int col = n0 + warp_n + na * 8 + (lane & 3) * 2;
            float2 o0, o1;
            o0.x = c[ma][na][0] + pb[col]     + pos[(size_t)tok0 * 512 + col];
            o0.y = c[ma][na][1] + pb[col + 1] + pos[(size_t)tok0 * 512 + col + 1];
            o1.x = c[ma][na][2] + pb[col]     + pos[(size_t)tok1 * 512 + col];
            o1.y = c[ma][na][3] + pb[col + 1] + pos[(size_t)tok1 * 512 + col + 1];
            *(float2*)(g_x + (size_t)r0 * 512 + col) = o0;
            *(float2*)(g_x + (size_t)r1 * 512 + col) = o1;
        }
    }
}

// ============================================================================
// generic TC GEMM (tf32): C = A @ B (+bias)(+gelu)(+resid g_x)
// CTA 128 x BN, BK=32, BN*4 threads (warp tile 32x32), double-buffered.
// Batched via blockIdx.z (z = bb*hc + hd).
// ============================================================================
template<int BN>
__global__ __launch_bounds__(BN * 4, 1)
void k_tc_nn(int aId, u64 aBatch, u64 aHead, int ldA,
             const float* __restrict__ Bext, int bId,
             u64 bBatch, u64 bHead, u64 bOff, int ldB,
             int cId, u64 cBatch, u64 cHead, u64 cOff, int ldC,
             int K, int hc,
             const float* __restrict__ bias, int addResid, int gelu) {
    constexpr int NT = BN * 4;           // threads
    constexpr int APASS = 256 / BN;      // A float4 loads/thread (2 or 4)
    constexpr int AROWS = NT / 8;        // A rows per pass (64 or 32)
    constexpr int BCH = BN / 4;          // float4 chunks per B row
    constexpr int BPAD = BN + 8;

    __shared__ __align__(16) float As[2][128 * 32];
    __shared__ __align__(16) float Bs[2][32 * BPAD];

    const int tid  = threadIdx.x;
    const int lane = tid & 31;
    const int wid  = tid >> 5;
    const int warp_m = (wid & 3) * 32;
    const int warp_n = (wid >> 2) * 32;
    const int m0 = blockIdx.y * 128;
    const int n0 = blockIdx.x * BN;

    const int z  = blockIdx.z;
    const int bb = z / hc;
    const int hd = z % hc;
    const float* A = buf(aId) + (size_t)bb * aBatch + (size_t)hd * aHead;
    const float* Bg = (bId < 0 ? Bext : buf(bId)) +
                      (size_t)bb * bBatch + (size_t)hd * bHead + bOff;
    float* C = buf(cId) + (size_t)bb * cBatch + (size_t)hd * cHead + cOff;

    const int aq = tid & 7;
    const int am = tid >> 3;             // 0..AROWS-1
    const int bc = tid % BCH;
    const int bk = tid / BCH;            // 0..15

    const int aw = am * 32 + ((aq ^ (am & 7)) << 2);  // AROWS multiple of 8
    const int bw = bk * BPAD + bc * 4;

    float c[2][4][4];
#pragma unroll
    for (int i = 0; i < 2; i++)
#pragma unroll
        for (int j = 0; j < 4; j++)
#pragma unroll
            for (int q = 0; q < 4; q++) c[i][j][q] = 0.0f;

    float4 pa[APASS], pv[2];

    // prologue
    {
#pragma unroll
        for (int t = 0; t < APASS; t++)
            pa[t] = *(const float4*)(A + (size_t)(m0 + am + t * AROWS) * ldA + aq * 4);
#pragma unroll
        for (int t = 0; t < 2; t++)
            pv[t] = *(const float4*)(Bg + (size_t)(bk + t * 16) * ldB + n0 + bc * 4);
#pragma unroll
        for (int t = 0; t < APASS; t++)
            *(float4*)&As[0][aw + t * AROWS * 32] = cvt4(pa[t]);
#pragma unroll
        for (int t = 0; t < 2; t++)
            *(float4*)&Bs[0][bw + t * 16 * BPAD] = cvt4(pv[t]);
    }
    __syncthreads();

    const int iters = K >> 5;
    int bsel = 0;
    for (int it = 0; it < iters; it++) {
        if (it < iters - 1) {
            int k0 = (it + 1) * 32;
#pragma unroll
            for (int t = 0; t < APASS; t++)
                pa[t] = *(const float4*)(A + (size_t)(m0 + am + t * AROWS) * ldA + k0 + aq * 4);
#pragma unroll
            for (int t = 0; t < 2; t++)
                pv[t] = *(const float4*)(Bg + (size_t)(k0 + bk + t * 16) * ldB + n0 + bc * 4);
        }

        const float* Asb = As[bsel];
        const float* Bsb = Bs[bsel];
#pragma unroll
        for (int kk = 0; kk < 4; kk++) {
            uint32_t af[2][4], bf[4][2];
            const int kq0 = kk * 2, kq1 = kk * 2 + 1;
            const int kb  = lane & 3;
#pragma unroll
            for (int ma = 0; ma < 2; ma++) {
                int r0 = warp_m + ma * 16 + (lane >> 2);
                int r1 = r0 + 8;
                af[ma][0] = ldu(&Asb[r0 * 32 + ((kq0 ^ (r0 & 7)) << 2) + kb]);
                af[ma][1] = ldu(&Asb[r1 * 32 + ((kq0 ^ (r1 & 7)) << 2) + kb]);
                af[ma][2] = ldu(&Asb[r0 * 32 + ((kq1 ^ (r0 & 7)) << 2) + kb]);
                af[ma][3] = ldu(&Asb[r1 * 32 + ((kq1 ^ (r1 & 7)) << 2) + kb]);
            }
#pragma unroll
            for (int na = 0; na < 4; na++) {
                int n = warp_n + na * 8 + (lane >> 2);
                bf[na][0] = ldu(&Bsb[(kk * 8 + kb) * BPAD + n]);
                bf[na][1] = ldu(&Bsb[(kk * 8 + 4 + kb) * BPAD + n]);
            }
#pragma unroll
            for (int ma = 0; ma < 2; ma++)
#pragma unroll
                for (int na = 0; na < 4; na++)
                    mma8(c[ma][na], af[ma], bf[na][0], bf[na][1]);
        }

        if (it < iters - 1) {
            int nb = bsel ^ 1;
#pragma unroll
            for (int t = 0; t < APASS; t++)
                *(float4*)&As[nb][aw + t * AROWS * 32] = cvt4(pa[t]);
#pragma unroll
            for (int t = 0; t < 2; t++)
                *(float4*)&Bs[nb][bw + t * 16 * BPAD] = cvt4(pv[t]);
            __syncthreads();
            bsel = nb;
        }
    }

    // epilogue
#pragma unroll
    for (int ma = 0; ma < 2; ma++) {
        int r0 = m0 + warp_m + ma * 16 + (lane >> 2);
        int r1 = r0 + 8;
#pragma unroll
        for (int na = 0; na < 4; na++) {
            int col = n0 + warp_n + na * 8 + (lane & 3) * 2;
            float v[4] = {c[ma][na][0], c[ma][na][1], c[ma][na][2], c[ma][na][3]};
            if (bias) {
                float b0 = bias[col], b1 = bias[col + 1];
                v[0] += b0; v[1] += b1; v[2] += b0; v[3] += b1;
            }
            if (gelu) {
#pragma unroll
                for (int q = 0; q < 4; q++)
                    v[q] = 0.5f * v[q] * (1.0f + erff(v[q] * 0.70710678118654752f));
            }
            if (addResid) {
                v[0] += g_x[(size_t)r0 * 512 + col];
                v[1] += g_x[(size_t)r0 * 512 + col + 1];
                v[2] += g_x[(size_t)r1 * 512 + col];
                v[3] += g_x[(size_t)r1 * 512 + col + 1];
            }
            *(float2*)(C + (size_t)r0 * ldC + col) = make_float2(v[0], v[1]);
            *(float2*)(C + (size_t)r1 * ldC + col) = make_float2(v[2], v[3]);
        }
    }
}

// ============================================================================
// attention scores (TC, TF32, K=64 single shot) — unchanged (validated R5)
// ============================================================================
__global__ __launch_bounds__(256, 1)
void k_tc_scores(const float* __restrict__ tbl, int qkvld, int inner, int hc) {
    __shared__ __align__(16) float As[128 * 64];
    __shared__ __align__(16) float Bs[64 * 136];

    const int tid  = threadIdx.x;
    const int lane = tid & 31;
    const int wid  = tid >> 5;
    const int warp_m = (wid & 3) * 32;
    const int warp_n = (wid >> 2) * 64;
    const int i0 = blockIdx.y * 128;
    const int j0 = blockIdx.x * 128;

    const int z = blockIdx.z;
    const int bb = z / hc, head = z % hc;
    const float* Qb = g_qkv + (size_t)bb * 1024 * qkvld + head * 64;
    const float* Kb = Qb + inner;

    {
        const int aq = tid & 15;
        const int am = tid >> 4;
#pragma unroll
        for (int t = 0; t < 8; t++) {
            int m = am + t * 16;
            float4 v = *(const float4*)(Qb + (size_t)(i0 + m) * qkvld + aq * 4);
            int p = (aq & 8) | ((aq ^ (m & 7)) & 7);
            *(float4*)&As[m * 64 + (p << 2)] = cvt4(v);
        }
    }
    {
        const int n = tid & 127;
        const int cc = tid >> 7;
#pragma unroll
        for (int t = 0; t < 8; t++) {
            int kq = cc + t * 2;
            float4 v = cvt4(*(const float4*)(Kb + (size_t)(j0 + n) * qkvld + kq * 4));
            Bs[(kq * 4 + 0) * 136 + n] = v.x;
            Bs[(kq * 4 + 1) * 136 + n] = v.y;
            Bs[(kq * 4 + 2) * 136 + n] = v.z;
            Bs[(kq * 4 + 3) * 136 + n] = v.w;
        }
    }
    __syncthreads();

    float c[2][8][4];
#pragma unroll
    for (int i = 0; i < 2; i++)
#pragma unroll
        for (int j = 0; j < 8; j++)
#pragma unroll
            for (int q = 0; q < 4; q++) c[i][j][q] = 0.0f;

#pragma unroll
    for (int kk = 0; kk < 8; kk++) {
        uint32_t af[2][4], bf[8][2];
        const int kq0 = kk * 2, kq1 = kk * 2 + 1;
        const int kb  = lane & 3;
#pragma unroll
        for (int ma = 0; ma < 2; ma++) {
            int r0 = warp_m + ma * 16 + (lane >> 2);
            int r1 = r0 + 8;
            int p00 = (kq0 & 8) | ((kq0 ^ (r0 & 7)) & 7);
            int p01 = (kq0 & 8) | ((kq0 ^ (r1 & 7)) & 7);
            int p10 = (kq1 & 8) | ((kq1 ^ (r0 & 7)) & 7);
            int p11 = (kq1 & 8) | ((kq1 ^ (r1 & 7)) & 7);
            af[ma][0] = ldu(&As[r0 * 64 + (p00 << 2) + kb]);
            af[ma][1] = ldu(&As[r1 * 64 + (p01 << 2) + kb]);
            af[ma][2] = ldu(&As[r0 * 64 + (p10 << 2) + kb]);
            af[ma][3] = ldu(&As[r1 * 64 + (p11 << 2) + kb]);
        }
#pragma unroll
        for (int na = 0; na < 8; na++) {
            int n = warp_n + na * 8 + (lane >> 2);
            bf[na][0] = ldu(&Bs[(kk * 8 + kb) * 136 + n]);
            bf[na][1] = ldu(&Bs[(kk * 8 + 4 + kb) * 136 + n]);
        }
#pragma unroll
        for (int ma = 0; ma < 2; ma++)
#pragma unroll
            for (int na = 0; na < 8; na++)
                mma8(c[ma][na], af[ma], bf[na][0], bf[na][1]);
    }

    float* Sp = g_attn + (size_t)z * 1048576;
#pragma unroll
    for (int ma = 0; ma < 2; ma++) {
        int r0 = i0 + warp_m + ma * 16 + (lane >> 2);
        int r1 = r0 + 8;
        int ih0 = r0 >> 5, iw0 = r0 & 31;
        int ih1 = r1 >> 5, iw1 = r1 & 31;
#pragma unroll
        for (int na = 0; na < 8; na++) {
            int jj = j0 + warp_n + na * 8 + (lane & 3) * 2;
            int jh0 = jj >> 5, jw0 = jj & 31;
            int jh1 = (jj + 1) >> 5, jw1 = (jj + 1) & 31;
            float2 o0, o1;
            o0.x = c[ma][na][0] * 0.125f +
                   tbl[(size_t)((ih0 - jh0 + 31) * 63 + (iw0 - jw0 + 31)) * hc + head];
            o0.y = c[ma][na][1] * 0.125f +
                   tbl[(size_t)((ih0 - jh1 + 31) * 63 + (iw0 - jw1 + 31)) * hc + head];
            o1.x = c[ma][na][2] * 0.125f +
                   tbl[(size_t)((ih1 - jh0 + 31) * 63 + (iw1 - jw0 + 31)) * hc + head];
            o1.y = c[ma][na][3] * 0.125f +
                   tbl[(size_t)((ih1 - jh1 + 31) * 63 + (iw1 - jw1 + 31)) * hc + head];
            *(float2*)(Sp + (size_t)r0 * 1024 + jj) = o0;
            *(float2*)(Sp + (size_t)r1 * 1024 + jj) = o1;
        }
    }
}

// ============================================================================
// row softmax over 1024 columns
// ============================================================================
__global__ void k_softmax() {
    __shared__ float sh[8];
    int tid = threadIdx.x;
    float* row = g_attn + (size_t)blockIdx.x * 1024;
    float4 v = ((float4*)row)[tid];
    float m = fmaxf(fmaxf(v.x, v.y), fmaxf(v.z, v.w));
#pragma unroll
    for (int o = 16; o; o >>= 1) m = fmaxf(m, __shfl_xor_sync(0xffffffffu, m, o));
    if ((tid & 31) == 0) sh[tid >> 5] = m;
    __syncthreads();
    float m8 = sh[0];
#pragma unroll
    for (int i = 1; i < 8; i++) m8 = fmaxf(m8, sh[i]);
    float4 e;
    e.x = __expf(v.x - m8); e.y = __expf(v.y - m8);
    e.z = __expf(v.z - m8); e.w = __expf(v.w - m8);
    float s = e.x + e.y + e.z + e.w;
#pragma unroll
    for (int o = 16; o; o >>= 1) s += __shfl_xor_sync(0xffffffffu, s, o);
    __syncthreads();
    if ((tid & 31) == 0) sh[tid >> 5] = s;
    __syncthreads();
    float tot = 0.f;
#pragma unroll
    for (int i = 0; i < 8; i++) tot += sh[i];
    float inv = 1.0f / tot;
    e.x *= inv; e.y *= inv; e.z *= inv; e.w *= inv;
    ((float4*)row)[tid] = e;
}

// ============================================================================
// LayerNorm over 512
// ============================================================================
__global__ void k_layernorm(const float* __restrict__ s, const float* __restrict__ b) {
    __shared__ float ssum[4], ssq[4];
    int tid = threadIdx.x;
    int row = blockIdx.x;
    float4 v = ((const float4*)(g_x + (size_t)row * 512))[tid];
    float sum = v.x + v.y + v.z + v.w;
    float sq  = v.x * v.x + v.y * v.y + v.z * v.z + v.w * v.w;
#pragma unroll
    for (int o = 16; o; o >>= 1) {
        sum += __shfl_xor_sync(0xffffffffu, sum, o);
        sq  += __shfl_xor_sync(0xffffffffu, sq, o);
    }
    if ((tid & 31) == 0) { ssum[tid >> 5] = sum; ssq[tid >> 5] = sq; }
    __syncthreads();
    float ts = ssum[0] + ssum[1] + ssum[2] + ssum[3];
    float tq = ssq[0] + ssq[1] + ssq[2] + ssq[3];
    float mean = ts * (1.0f / 512.0f);
    float var  = tq * (1.0f / 512.0f) - mean * mean;
    float rstd = rsqrtf(var + 1e-5f);
    int d = tid << 2;
    float4 sv = *(const float4*)(s + d);
    float4 bv = *(const float4*)(b + d);
    float4 o;
    o.x = (v.x - mean) * rstd * sv.x + bv.x;
    o.y = (v.y - mean) * rstd * sv.y + bv.y;
    o.z = (v.z - mean) * rstd * sv.z + bv.z;
    o.w = (v.w - mean) * rstd * sv.w + bv.w;
    ((float4*)(g_xn + (size_t)row * 512))[tid] = o;
}

// ============================================================================
// final layout: out[b][d][n] = g_x[b][n][d]
// ============================================================================
__global__ void k_out(float* __restrict__ out) {
    __shared__ float t[32][33];
    int bb = blockIdx.z;
    int n0 = blockIdx.x * 32, d0 = blockIdx.y * 32;
    int tx = threadIdx.x, ty = threadIdx.y;
#pragma unroll
    for (int i = 0; i < 32; i += 8)
        t[ty + i][tx] = g_x[((size_t)bb * 1024 + n0 + ty + i) * 512 + d0 + tx];
    __syncthreads();
#pragma unroll
    for (int i = 0; i < 32; i += 8)
        out[((size_t)bb * 512 + d0 + ty + i) * 1024 + n0 + tx] = t[tx][ty + i];
}

// ============================================================================
// host orchestration
// ============================================================================
extern "C" void kernel_launch(void* const* d_in, const int* in_sizes, int n_in,
                              void* d_out, int out_size) {
    const float *img = 0, *patch_w = 0, *patch_b = 0, *pos_emb = 0;
    const float *ln1_s = 0, *ln1_b = 0, *ln2_s = 0, *ln2_b = 0;
    const float *qkv_w[3] = {0, 0, 0}, *out_w[3] = {0, 0, 0}, *out_b[3] = {0, 0, 0};
    const float *tbl[3] = {0, 0, 0};
    const float *ff_w1 = 0, *ff_b1 = 0, *ff_w2 = 0, *ff_b2 = 0;
    int c512 = 0, c1536 = 0, c393 = 0;
    for (int i = 0; i < n_in; i++) {
        const float* p = (const float*)d_in[i];
        switch (in_sizes[i]) {
            case 134217728: img = p; break;
            case 16777216: patch_w = p; break;
            case 524288:   pos_emb = p; break;
            case 512: {
                const float** t[4] = {&patch_b, &out_b[0], &out_b[1], &out_b[2]};
                if (c512 < 4) *t[c512] = p;
                c512++;
            } break;
            case 1536: {
                const float** t[5] = {&ln1_s, &ln1_b, &ln2_s, &ln2_b, &ff_b2};
                if (c1536 < 5) *t[c1536] = p;
                c1536++;
            } break;
            case 768:    ff_b1 = p; break;
            case 196608: qkv_w[0] = p; break;
            case 393216: {
                const float** t[3] = {&qkv_w[1], &ff_w1, &ff_w2};
                if (c393 < 3) *t[c393] = p;
                c393++;
            } break;
            case 786432: qkv_w[2] = p; break;
            case 65536:  out_w[0] = p; break;
            case 131072: out_w[1] = p; break;
            case 262144: out_w[2] = p; break;
            case 7938:   tbl[0] = p; break;
            case 15876:  tbl[1] = p; break;
            case 31752:  tbl[2] = p; break;
            default: break;
        }
    }

    bool ok = img && patch_w && patch_b && pos_emb && ln1_s && ln1_b && ln2_s &&
              ln2_b && ff_w1 && ff_b1 && ff_w2 && ff_b2;
    for (int l = 0; l < 3; l++)
        ok = ok && qkv_w[l] && out_w[l] && out_b[l] && tbl[l];
    if (!ok) {
        k_zero<<<(out_size + 255) / 256, 256>>>((float*)d_out, out_size);
        return;
    }

    k_permute_pw<<<(32768 * 128 + 255) / 256, 256>>>(patch_w);
    k_patch_tc<<<dim3(4, 32), 512>>>(img, patch_b, pos_emb);

    const int heads[3] = {2, 4, 8};
    for (int l = 0; l < 3; l++) {
        int h = heads[l];
        int inner = 64 * h;
        int qkvld = 3 * inner;

        // ---- attention ----
        k_layernorm<<<4096, 128>>>(ln1_s + l * 512, ln1_b + l * 512);
        k_tc_nn<128><<<dim3(qkvld / 128, 32, 1), 512>>>(
            BUF_XN, 0ULL, 0ULL, 512,
            qkv_w[l], -1, 0ULL, 0ULL, 0ULL, qkvld,
            BUF_QKV, 0ULL, 0ULL, 0ULL, qkvld,
            512, 1, nullptr, 0, 0);
        k_tc_scores<<<dim3(8, 8, 4 * h), 256>>>(tbl[l], qkvld, inner, h);
        k_softmax<<<4 * h * 1024, 256>>>();
        k_tc_nn<64><<<dim3(1, 8, 4 * h), 256>>>(
            BUF_ATT, (u64)h * 1048576ULL, 1048576ULL, 1024,
            nullptr, BUF_QKV, (u64)1024 * qkvld, 64ULL,
            (u64)(2 * inner), qkvld,
            BUF_O, (u64)1024 * inner, 64ULL, 0ULL, inner,
            1024, h, nullptr, 0, 0);
        k_tc_nn<128><<<dim3(4, 32, 1), 512>>>(
            BUF_O, 0ULL, 0ULL, inner,
            out_w[l], -1, 0ULL, 0ULL, 0ULL, 512,
            BUF_X, 0ULL, 0ULL, 0ULL, 512,
            inner, 1, out_b[l], 1, 0);

        // ---- feed-forward ----
        k_layernorm<<<4096, 128>>>(ln2_s + l * 512, ln2_b + l * 512);
        k_tc_nn<128><<<dim3(2, 32, 1), 512>>>(
            BUF_XN, 0ULL, 0ULL, 512,
            ff_w1 + (size_t)l * 512 * 256, -1, 0ULL, 0ULL, 0ULL, 256,
            BUF_H, 0ULL, 0ULL, 0ULL, 256,
            512, 1, ff_b1 + l * 256, 0, 1);
        k_tc_nn<128><<<dim3(4, 32, 1), 512>>>(
            BUF_H, 0ULL, 0ULL, 256,
            ff_w2 + (size_t)l * 256 * 512, -1, 0ULL, 0ULL, 0ULL, 512,
            BUF_X, 0ULL, 0ULL, 0ULL, 512,
            256, 1, ff_b2 + l * 512, 1, 0);
    }

    k_out<<<dim3(32, 16, 4), dim3(32, 8)>>>((float*)d_out);
}

// round 8
// speedup vs baseline: 1.4622x; 1.1161x over previous
#include <cuda_runtime.h>
#include <math.h>
#include <stdint.h>

typedef unsigned long long u64;

// ---------------- problem constants ----------------
// B=4, C=128, H=W=512, P=16, GH=GW=32, N=1024, PATCH_DIM=32768, DIM=512,
// MLP=256, DH=64, HEADS=(2,4,8), NUM_REL=3969

// ---------------- scratch (device globals) ----------------
__device__ __align__(16) float g_pw2[32768 * 512];   // permuted patch_w (64 MB)
__device__ __align__(16) float g_x[4096 * 512];      // residual stream
__device__ __align__(16) float g_xn[4096 * 512];     // LN output
__device__ __align__(16) float g_qkv[4096 * 1536];   // qkv (max inner=512)
__device__ __align__(16) float g_attn[33554432];     // scores / patch partials
__device__ __align__(16) float g_o[4096 * 512];      // attention output
__device__ __align__(16) float g_h[4096 * 256];      // FFN hidden

#define BUF_X   0
#define BUF_XN  1
#define BUF_QKV 2
#define BUF_O   3
#define BUF_H   4
#define BUF_ATT 5
__device__ __forceinline__ float* buf(int id) {
    switch (id) {
        case BUF_X:   return g_x;
        case BUF_XN:  return g_xn;
        case BUF_QKV: return g_qkv;
        case BUF_O:   return g_o;
        case BUF_ATT: return g_attn;
        default:      return g_h;
    }
}

// ============================================================================
__global__ void k_zero(float* o, int n) {
    int i = blockIdx.x * blockDim.x + threadIdx.x;
    if (i < n) o[i] = 0.0f;
}

// ============================================================================
// permute patch_w rows:  in row (p1*16+p2)*128 + c  ->  out row c*256 + p1*16+p2
// ============================================================================
__global__ void k_permute_pw(const float* __restrict__ pw) {
    int idx = blockIdx.x * blockDim.x + threadIdx.x;
    if (idx >= 32768 * 128) return;
    int r  = idx >> 7;
    int d4 = idx & 127;
    int p  = r >> 7;
    int c  = r & 127;
    int rout = (c << 8) + p;
    float4 v = ((const float4*)pw)[(size_t)r * 128 + d4];
    ((float4*)g_pw2)[(size_t)rout * 128 + d4] = v;
}

// ============================================================================
// TF32 helpers
// ============================================================================
__device__ __forceinline__ uint32_t f2tf(float f) {
    uint32_t r;
    asm("cvt.rna.tf32.f32 %0, %1;" : "=r"(r) : "f"(f));
    return r;
}
__device__ __forceinline__ float4 cvt4(float4 v) {
    v.x = __uint_as_float(f2tf(v.x));
    v.y = __uint_as_float(f2tf(v.y));
    v.z = __uint_as_float(f2tf(v.z));
    v.w = __uint_as_float(f2tf(v.w));
    return v;
}
__device__ __forceinline__ void mma8(float* c, const uint32_t* a,
                                     uint32_t b0, uint32_t b1) {
    asm("mma.sync.aligned.m16n8k8.row.col.f32.tf32.tf32.f32 "
        "{%0,%1,%2,%3},{%4,%5,%6,%7},{%8,%9},{%0,%1,%2,%3};"
        : "+f"(c[0]), "+f"(c[1]), "+f"(c[2]), "+f"(c[3])
        : "r"(a[0]), "r"(a[1]), "r"(a[2]), "r"(a[3]), "r"(b0), "r"(b1));
}
__device__ __forceinline__ uint32_t ldu(const float* p) {
    return __float_as_uint(*p);
}

// ============================================================================
// patch embed GEMM, split-K partials (TC tf32, warp tile 64x64):
//   part[z][m][d] = sum_{k in half z} A[m][k'] * pw2[k'][d]
// CTA 256m x 128n, 8 warps (4m x 2n, 64x64 each), BK=32, double-buffered.
// partials land in g_attn (free until attention scores).
// ============================================================================
__global__ __launch_bounds__(256, 1)
void k_patch_tc(const float* __restrict__ img) {
    extern __shared__ float sm[];
    // layout: As[2][256*32] then Bs[2][32*136]
    float* Asm = sm;                   // 2 * 8192 floats
    float* Bsm = sm + 2 * 8192;        // 2 * 4352 floats

    const int tid  = threadIdx.x;
    const int lane = tid & 31;
    const int wid  = tid >> 5;
    const int warp_m = (wid & 3) * 64;
    const int warp_n = (wid >> 2) * 64;
    const int m0 = blockIdx.y * 256;
    const int n0 = blockIdx.x * 128;
    const int kHalf = blockIdx.z;      // 0 or 1
    const int kBase = kHalf * 16384;

    // A gather: aq = k-quad (0..7), am = m row (0..31), rows am + 32t
    const int aq = tid & 7;
    const int am = tid >> 3;
    // B loader: bc = n chunk (0..31), bk = k row (0..7), rows bk + 8t
    const int bc = tid & 31;
    const int bk = tid >> 5;

    const float* abase[8];
#pragma unroll
    for (int t = 0; t < 8; t++) {
        int m_g = m0 + am + t * 32;
        int bb  = m_g >> 10;
        int tok = m_g & 1023;
        int gh = tok >> 5, gw = tok & 31;
        abase[t] = img + (size_t)bb * 33554432 + (size_t)(gh * 16) * 512 + gw * 16;
    }
    const float* bbase = g_pw2 + n0 + bc * 4;

    const int aw = am * 32 + ((aq ^ (am & 7)) << 2);   // (am+32t)&7 == am&7
    const int bw = bk * 136 + bc * 4;

    float c[4][8][4];
#pragma unroll
    for (int i = 0; i < 4; i++)
#pragma unroll
        for (int j = 0; j < 8; j++)
#pragma unroll
            for (int q = 0; q < 4; q++) c[i][j][q] = 0.0f;

    float4 pa[8], pv[4];

    // ---- prologue ----
    {
        int k = kBase + aq * 4;
        int cc = k >> 8, rem = k & 255;
        const size_t aoff = (size_t)cc * 262144 + (rem >> 4) * 512 + (rem & 15);
#pragma unroll
        for (int t = 0; t < 8; t++) pa[t] = *(const float4*)(abase[t] + aoff);
#pragma unroll
        for (int t = 0; t < 4; t++)
            pv[t] = *(const float4*)(bbase + (size_t)(kBase + bk + t * 8) * 512);
#pragma unroll
        for (int t = 0; t < 8; t++) *(float4*)&Asm[aw + t * 1024] = cvt4(pa[t]);
#pragma unroll
        for (int t = 0; t < 4; t++) *(float4*)&Bsm[bw + t * 8 * 136] = cvt4(pv[t]);
    }
    __syncthreads();

    int bsel = 0;
    for (int it = 0; it < 512; it++) {
        if (it < 511) {
            int k0 = kBase + (it + 1) * 32;
            int k = k0 + aq * 4;
            int cc = k >> 8, rem = k & 255;
            const size_t aoff = (size_t)cc * 262144 + (rem >> 4) * 512 + (rem & 15);
#pragma unroll
            for (int t = 0; t < 8; t++) pa[t] = *(const float4*)(abase[t] + aoff);
#pragma unroll
            for (int t = 0; t < 4; t++)
                pv[t] = *(const float4*)(bbase + (size_t)(k0 + bk + t * 8) * 512);
        }

        const float* Asb = Asm + bsel * 8192;
        const float* Bsb = Bsm + bsel * 4352;
#pragma unroll
        for (int kk = 0; kk < 4; kk++) {
            uint32_t af[4][4], bf[8][2];
            const int kq0 = kk * 2, kq1 = kk * 2 + 1;
            const int kb  = lane & 3;
#pragma unroll
            for (int ma = 0; ma < 4; ma++) {
                int r0 = warp_m + ma * 16 + (lane >> 2);
                int r1 = r0 + 8;
                af[ma][0] = ldu(&Asb[r0 * 32 + ((kq0 ^ (r0 & 7)) << 2) + kb]);
                af[ma][1] = ldu(&Asb[r1 * 32 + ((kq0 ^ (r1 & 7)) << 2) + kb]);
                af[ma][2] = ldu(&Asb[r0 * 32 + ((kq1 ^ (r0 & 7)) << 2) + kb]);
                af[ma][3] = ldu(&Asb[r1 * 32 + ((kq1 ^ (r1 & 7)) << 2) + kb]);
            }
#pragma unroll
            for (int na = 0; na < 8; na++) {
                int n = warp_n + na * 8 + (lane >> 2);
                bf[na][0] = ldu(&Bsb[(kk * 8 + kb) * 136 + n]);
                bf[na][1] = ldu(&Bsb[(kk * 8 + 4 + kb) * 136 + n]);
            }
#pragma unroll
            for (int ma = 0; ma < 4; ma++)
#pragma unroll
                for (int na = 0; na < 8; na++)
                    mma8(c[ma][na], af[ma], bf[na][0], bf[na][1]);
        }

        if (it < 511) {
            int nb = bsel ^ 1;
#pragma unroll
            for (int t = 0; t < 8; t++)
                *(float4*)&Asm[nb * 8192 + aw + t * 1024] = cvt4(pa[t]);
#pragma unroll
            for (int t = 0; t < 4; t++)
                *(float4*)&Bsm[nb * 4352 + bw + t * 8 * 136] = cvt4(pv[t]);
            __syncthreads();
            bsel = nb;
        }
    }

    // ---- epilogue: write raw partials ----
    float* part = g_attn + (size_t)kHalf * 2097152;
#pragma unroll
    for (int ma = 0; ma < 4; ma++) {
        int r0 = m0 + warp_m + ma * 16 + (lane >> 2);
        int r1 = r0 + 8;
#pragma unroll
        for (int na = 0; na < 8; na++) {
            int col = n0 + warp_n + na * 8 + (lane & 3) * 2;
            *(float2*)(part + (size_t)r0 * 512 + col) = make_float2(c[ma][na][0], c[ma][na][1]);
            *(float2*)(part + (size_t)r1 * 512 + col) = make_float2(c[ma][na][2], c[ma][na][3]);
        }
    }
}

// ============================================================================
// combine split-K partials:  g_x = p0 + p1 + patch_b + pos_emb
// ============================================================================
__global__ void k_patch_sum(const float* __restrict__ pb,
                            const float* __restrict__ pos) {
    int idx = blockIdx.x * blockDim.x + threadIdx.x;   // 4096*128 float4
    if (idx >= 4096 * 128) return;
    int row = idx >> 7;
    int c4  = idx & 127;
    int tok = row & 1023;
    float4 a = ((const float4*)g_attn)[idx];
    float4 b = ((const float4*)(g_attn + 2097152))[idx];
    float4 pb4 = ((const float4*)pb)[c4];
    float4 ps  = ((const float4*)pos)[(size_t)tok * 128 + c4];
    float4 o;
    o.x = a.x + b.x + pb4.x + ps.x;
    o.y = a.y + b.y + pb4.y + ps.y;
    o.z = a.z + b.z + pb4.z + ps.z;
    o.w = a.w + b.w + pb4.w + ps.w;
    ((float4*)g_x)[idx] = o;
}

// ============================================================================
// generic TC GEMM (tf32): C = A @ B (+bias)(+gelu)(+resid g_x)
// CTA 128 x BN, BK=32, BN*4 threads (warp tile 32x32), double-buffered.
// Batched via blockIdx.z (z = bb*hc + hd).  (unchanged, validated R7)
// ============================================================================
template<int BN>
__global__ __launch_bounds__(BN * 4, 1)
void k_tc_nn(int aId, u64 aBatch, u64 aHead, int ldA,
             const float* __restrict__ Bext, int bId,
             u64 bBatch, u64 bHead, u64 bOff, int ldB,
             int cId, u64 cBatch, u64 cHead, u64 cOff, int ldC,
             int K, int hc,
             const float* __restrict__ bias, int addResid, int gelu) {
    constexpr int NT = BN * 4;
    constexpr int APASS = 256 / BN;
    constexpr int AROWS = NT / 8;
    constexpr int BCH = BN / 4;
    constexpr int BPAD = BN + 8;

    __shared__ __align__(16) float As[2][128 * 32];
    __shared__ __align__(16) float Bs[2][32 * BPAD];

    const int tid  = threadIdx.x;
    const int lane = tid & 31;
    const int wid  = tid >> 5;
    const int warp_m = (wid & 3) * 32;
    const int warp_n = (wid >> 2) * 32;
    const int m0 = blockIdx.y * 128;
    const int n0 = blockIdx.x * BN;

    const int z  = blockIdx.z;
    const int bb = z / hc;
    const int hd = z % hc;
    const float* A = buf(aId) + (size_t)bb * aBatch + (size_t)hd * aHead;
    const float* Bg = (bId < 0 ? Bext : buf(bId)) +
                      (size_t)bb * bBatch + (size_t)hd * bHead + bOff;
    float* C = buf(cId) + (size_t)bb * cBatch + (size_t)hd * cHead + cOff;

    const int aq = tid & 7;
    const int am = tid >> 3;
    const int bc = tid % BCH;
    const int bk = tid / BCH;

    const int aw = am * 32 + ((aq ^ (am & 7)) << 2);
    const int bw = bk * BPAD + bc * 4;

    float c[2][4][4];
#pragma unroll
    for (int i = 0; i < 2; i++)
#pragma unroll
        for (int j = 0; j < 4; j++)
#pragma unroll
            for (int q = 0; q < 4; q++) c[i][j][q] = 0.0f;

    float4 pa[APASS], pv[2];

    {
#pragma unroll
        for (int t = 0; t < APASS; t++)
            pa[t] = *(const float4*)(A + (size_t)(m0 + am + t * AROWS) * ldA + aq * 4);
#pragma unroll
        for (int t = 0; t < 2; t++)
            pv[t] = *(const float4*)(Bg + (size_t)(bk + t * 16) * ldB + n0 + bc * 4);
#pragma unroll
        for (int t = 0; t < APASS; t++)
            *(float4*)&As[0][aw + t * AROWS * 32] = cvt4(pa[t]);
#pragma unroll
        for (int t = 0; t < 2; t++)
            *(float4*)&Bs[0][bw + t * 16 * BPAD] = cvt4(pv[t]);
    }
    __syncthreads();

    const int iters = K >> 5;
    int bsel = 0;
    for (int it = 0; it < iters; it++) {
        if (it < iters - 1) {
            int k0 = (it + 1) * 32;
#pragma unroll
            for (int t = 0; t < APASS; t++)
                pa[t] = *(const float4*)(A + (size_t)(m0 + am + t * AROWS) * ldA + k0 + aq * 4);
#pragma unroll
            for (int t = 0; t < 2; t++)
                pv[t] = *(const float4*)(Bg + (size_t)(k0 + bk + t * 16) * ldB + n0 + bc * 4);
        }

        const float* Asb = As[bsel];
        const float* Bsb = Bs[bsel];
#pragma unroll
        for (int kk = 0; kk < 4; kk++) {
            uint32_t af[2][4], bf[4][2];
            const int kq0 = kk * 2, kq1 = kk * 2 + 1;
            const int kb  = lane & 3;
#pragma unroll
            for (int ma = 0; ma < 2; ma++) {
                int r0 = warp_m + ma * 16 + (lane >> 2);
                int r1 = r0 + 8;
                af[ma][0] = ldu(&Asb[r0 * 32 + ((kq0 ^ (r0 & 7)) << 2) + kb]);
                af[ma][1] = ldu(&Asb[r1 * 32 + ((kq0 ^ (r1 & 7)) << 2) + kb]);
                af[ma][2] = ldu(&Asb[r0 * 32 + ((kq1 ^ (r0 & 7)) << 2) + kb]);
                af[ma][3] = ldu(&Asb[r1 * 32 + ((kq1 ^ (r1 & 7)) << 2) + kb]);
            }
#pragma unroll
            for (int na = 0; na < 4; na++) {
                int n = warp_n + na * 8 + (lane >> 2);
                bf[na][0] = ldu(&Bsb[(kk * 8 + kb) * BPAD + n]);
                bf[na][1] = ldu(&Bsb[(kk * 8 + 4 + kb) * BPAD + n]);
            }
#pragma unroll
            for (int ma = 0; ma < 2; ma++)
#pragma unroll
                for (int na = 0; na < 4; na++)
                    mma8(c[ma][na], af[ma], bf[na][0], bf[na][1]);
        }

        if (it < iters - 1) {
            int nb = bsel ^ 1;
#pragma unroll
            for (int t = 0; t < APASS; t++)
                *(float4*)&As[nb][aw + t * AROWS * 32] = cvt4(pa[t]);
#pragma unroll
            for (int t = 0; t < 2; t++)
                *(float4*)&Bs[nb][bw + t * 16 * BPAD] = cvt4(pv[t]);
            __syncthreads();
            bsel = nb;
        }
    }

#pragma unroll
    for (int ma = 0; ma < 2; ma++) {
        int r0 = m0 + warp_m + ma * 16 + (lane >> 2);
        int r1 = r0 + 8;
#pragma unroll
        for (int na = 0; na < 4; na++) {
            int col = n0 + warp_n + na * 8 + (lane & 3) * 2;
            float v[4] = {c[ma][na][0], c[ma][na][1], c[ma][na][2], c[ma][na][3]};
            if (bias) {
                float b0 = bias[col], b1 = bias[col + 1];
                v[0] += b0; v[1] += b1; v[2] += b0; v[3] += b1;
            }
            if (gelu) {
#pragma unroll
                for (int q = 0; q < 4; q++)
                    v[q] = 0.5f * v[q] * (1.0f + erff(v[q] * 0.70710678118654752f));
            }
            if (addResid) {
                v[0] += g_x[(size_t)r0 * 512 + col];
                v[1] += g_x[(size_t)r0 * 512 + col + 1];
                v[2] += g_x[(size_t)r1 * 512 + col];
                v[3] += g_x[(size_t)r1 * 512 + col + 1];
            }
            *(float2*)(C + (size_t)r0 * ldC + col) = make_float2(v[0], v[1]);
            *(float2*)(C + (size_t)r1 * ldC + col) = make_float2(v[2], v[3]);
        }
    }
}

// ============================================================================
// attention scores (TC, TF32, K=64 single shot) — unchanged (validated R5)
// ============================================================================
__global__ __launch_bounds__(256, 1)
void k_tc_scores(const float* __restrict__ tbl, int qkvld, int inner, int hc) {
    __shared__ __align__(16) float As[128 * 64];
    __shared__ __align__(16) float Bs[64 * 136];

    const int tid  = threadIdx.x;
    const int lane = tid & 31;
    const int wid  = tid >> 5;
    const int warp_m = (wid & 3) * 32;
    const int warp_n = (wid >> 2) * 64;
    const int i0 = blockIdx.y * 128;
    const int j0 = blockIdx.x * 128;

    const int z = blockIdx.z;
    const int bb = z / hc, head = z % hc;
    const float* Qb = g_qkv + (size_t)bb * 1024 * qkvld + head * 64;
    const float* Kb = Qb + inner;

    {
        const int aq = tid & 15;
        const int am = tid >> 4;
#pragma unroll
        for (int t = 0; t < 8; t++) {
            int m = am + t * 16;
            float4 v = *(const float4*)(Qb + (size_t)(i0 + m) * qkvld + aq * 4);
            int p = (aq & 8) | ((aq ^ (m & 7)) & 7);
            *(float4*)&As[m * 64 + (p << 2)] = cvt4(v);
        }
    }
    {
        const int n = tid & 127;
        const int cc = tid >> 7;
#pragma unroll
        for (int t = 0; t < 8; t++) {
            int kq = cc + t * 2;
            float4 v = cvt4(*(const float4*)(Kb + (size_t)(j0 + n) * qkvld + kq * 4));
            Bs[(kq * 4 + 0) * 136 + n] = v.x;
            Bs[(kq * 4 + 1) * 136 + n] = v.y;
            Bs[(kq * 4 + 2) * 136 + n] = v.z;
            Bs[(kq * 4 + 3) * 136 + n] = v.w;
        }
    }
    __syncthreads();

    float c[2][8][4];
#pragma unroll
    for (int i = 0; i < 2; i++)
#pragma unroll
        for (int j = 0; j < 8; j++)
#pragma unroll
            for (int q = 0; q < 4; q++) c[i][j][q] = 0.0f;

#pragma unroll
    for (int kk = 0; kk < 8; kk++) {
        uint32_t af[2][4], bf[8][2];
        const int kq0 = kk * 2, kq1 = kk * 2 + 1;
        const int kb  = lane & 3;
#pragma unroll
        for (int ma = 0; ma < 2; ma++) {
            int r0 = warp_m + ma * 16 + (lane >> 2);
            int r1 = r0 + 8;
            int p00 = (kq0 & 8) | ((kq0 ^ (r0 & 7)) & 7);
            int p01 = (kq0 & 8) | ((kq0 ^ (r1 & 7)) & 7);
            int p10 = (kq1 & 8) | ((kq1 ^ (r0 & 7)) & 7);
            int p11 = (kq1 & 8) | ((kq1 ^ (r1 & 7)) & 7);
            af[ma][0] = ldu(&As[r0 * 64 + (p00 << 2) + kb]);
            af[ma][1] = ldu(&As[r1 * 64 + (p01 << 2) + kb]);
            af[ma][2] = ldu(&As[r0 * 64 + (p10 << 2) + kb]);
            af[ma][3] = ldu(&As[r1 * 64 + (p11 << 2) + kb]);
        }
#pragma unroll
        for (int na = 0; na < 8; na++) {
            int n = warp_n + na * 8 + (lane >> 2);
            bf[na][0] = ldu(&Bs[(kk * 8 + kb) * 136 + n]);
            bf[na][1] = ldu(&Bs[(kk * 8 + 4 + kb) * 136 + n]);
        }
#pragma unroll
        for (int ma = 0; ma < 2; ma++)
#pragma unroll
            for (int na = 0; na < 8; na++)
                mma8(c[ma][na], af[ma], bf[na][0], bf[na][1]);
    }

    float* Sp = g_attn + (size_t)z * 1048576;
#pragma unroll
    for (int ma = 0; ma < 2; ma++) {
        int r0 = i0 + warp_m + ma * 16 + (lane >> 2);
        int r1 = r0 + 8;
        int ih0 = r0 >> 5, iw0 = r0 & 31;
        int ih1 = r1 >> 5, iw1 = r1 & 31;
#pragma unroll
        for (int na = 0; na < 8; na++) {
            int jj = j0 + warp_n + na * 8 + (lane & 3) * 2;
            int jh0 = jj >> 5, jw0 = jj & 31;
            int jh1 = (jj + 1) >> 5, jw1 = (jj + 1) & 31;
            float2 o0, o1;
            o0.x = c[ma][na][0] * 0.125f +
                   tbl[(size_t)((ih0 - jh0 + 31) * 63 + (iw0 - jw0 + 31)) * hc + head];
            o0.y = c[ma][na][1] * 0.125f +
                   tbl[(size_t)((ih0 - jh1 + 31) * 63 + (iw0 - jw1 + 31)) * hc + head];
            o1.x = c[ma][na][2] * 0.125f +
                   tbl[(size_t)((ih1 - jh0 + 31) * 63 + (iw1 - jw0 + 31)) * hc + head];
            o1.y = c[ma][na][3] * 0.125f +
                   tbl[(size_t)((ih1 - jh1 + 31) * 63 + (iw1 - jw1 + 31)) * hc + head];
            *(float2*)(Sp + (size_t)r0 * 1024 + jj) = o0;
            *(float2*)(Sp + (size_t)r1 * 1024 + jj) = o1;
        }
    }
}

// ============================================================================
// row softmax over 1024 columns
// ============================================================================
__global__ void k_softmax() {
    __shared__ float sh[8];
    int tid = threadIdx.x;
    float* row = g_attn + (size_t)blockIdx.x * 1024;
    float4 v = ((float4*)row)[tid];
    float m = fmaxf(fmaxf(v.x, v.y), fmaxf(v.z, v.w));
#pragma unroll
    for (int o = 16; o; o >>= 1) m = fmaxf(m, __shfl_xor_sync(0xffffffffu, m, o));
    if ((tid & 31) == 0) sh[tid >> 5] = m;
    __syncthreads();
    float m8 = sh[0];
#pragma unroll
    for (int i = 1; i < 8; i++) m8 = fmaxf(m8, sh[i]);
    float4 e;
    e.x = __expf(v.x - m8); e.y = __expf(v.y - m8);
    e.z = __expf(v.z - m8); e.w = __expf(v.w - m8);
    float s = e.x + e.y + e.z + e.w;
#pragma unroll
    for (int o = 16; o; o >>= 1) s += __shfl_xor_sync(0xffffffffu, s, o);
    __syncthreads();
    if ((tid & 31) == 0) sh[tid >> 5] = s;
    __syncthreads();
    float tot = 0.f;
#pragma unroll
    for (int i = 0; i < 8; i++) tot += sh[i];
    float inv = 1.0f / tot;
    e.x *= inv; e.y *= inv; e.z *= inv; e.w *= inv;
    ((float4*)row)[tid] = e;
}

// ============================================================================
// LayerNorm over 512
// ============================================================================
__global__ void k_layernorm(const float* __restrict__ s, const float* __restrict__ b) {
    __shared__ float ssum[4], ssq[4];
    int tid = threadIdx.x;
    int row = blockIdx.x;
    float4 v = ((const float4*)(g_x + (size_t)row * 512))[tid];
    float sum = v.x + v.y + v.z + v.w;
    float sq  = v.x * v.x + v.y * v.y + v.z * v.z + v.w * v.w;
#pragma unroll
    for (int o = 16; o; o >>= 1) {
        sum += __shfl_xor_sync(0xffffffffu, sum, o);
        sq  += __shfl_xor_sync(0xffffffffu, sq, o);
    }
    if ((tid & 31) == 0) { ssum[tid >> 5] = sum; ssq[tid >> 5] = sq; }
    __syncthreads();
    float ts = ssum[0] + ssum[1] + ssum[2] + ssum[3];
    float tq = ssq[0] + ssq[1] + ssq[2] + ssq[3];
    float mean = ts * (1.0f / 512.0f);
    float var  = tq * (1.0f / 512.0f) - mean * mean;
    float rstd = rsqrtf(var + 1e-5f);
    int d = tid << 2;
    float4 sv = *(const float4*)(s + d);
    float4 bv = *(const float4*)(b + d);
    float4 o;
    o.x = (v.x - mean) * rstd * sv.x + bv.x;
    o.y = (v.y - mean) * rstd * sv.y + bv.y;
    o.z = (v.z - mean) * rstd * sv.z + bv.z;
    o.w = (v.w - mean) * rstd * sv.w + bv.w;
    ((float4*)(g_xn + (size_t)row * 512))[tid] = o;
}

// ============================================================================
// final layout: out[b][d][n] = g_x[b][n][d]
// ============================================================================
__global__ void k_out(float* __restrict__ out) {
    __shared__ float t[32][33];
    int bb = blockIdx.z;
    int n0 = blockIdx.x * 32, d0 = blockIdx.y * 32;
    int tx = threadIdx.x, ty = threadIdx.y;
#pragma unroll
    for (int i = 0; i < 32; i += 8)
        t[ty + i][tx] = g_x[((size_t)bb * 1024 + n0 + ty + i) * 512 + d0 + tx];
    __syncthreads();
#pragma unroll
    for (int i = 0; i < 32; i += 8)
        out[((size_t)bb * 512 + d0 + ty + i) * 1024 + n0 + tx] = t[tx][ty + i];
}

// ============================================================================
// host orchestration
// ============================================================================
extern "C" void kernel_launch(void* const* d_in, const int* in_sizes, int n_in,
                              void* d_out, int out_size) {
    const float *img = 0, *patch_w = 0, *patch_b = 0, *pos_emb = 0;
    const float *ln1_s = 0, *ln1_b = 0, *ln2_s = 0, *ln2_b = 0;
    const float *qkv_w[3] = {0, 0, 0}, *out_w[3] = {0, 0, 0}, *out_b[3] = {0, 0, 0};
    const float *tbl[3] = {0, 0, 0};
    const float *ff_w1 = 0, *ff_b1 = 0, *ff_w2 = 0, *ff_b2 = 0;
    int c512 = 0, c1536 = 0, c393 = 0;
    for (int i = 0; i < n_in; i++) {
        const float* p = (const float*)d_in[i];
        switch (in_sizes[i]) {
            case 134217728: img = p; break;
            case 16777216: patch_w = p; break;
            case 524288:   pos_emb = p; break;
            case 512: {
                const float** t[4] = {&patch_b, &out_b[0], &out_b[1], &out_b[2]};
                if (c512 < 4) *t[c512] = p;
                c512++;
            } break;
            case 1536: {
                const float** t[5] = {&ln1_s, &ln1_b, &ln2_s, &ln2_b, &ff_b2};
                if (c1536 < 5) *t[c1536] = p;
                c1536++;
            } break;
            case 768:    ff_b1 = p; break;
            case 196608: qkv_w[0] = p; break;
            case 393216: {
                const float** t[3] = {&qkv_w[1], &ff_w1, &ff_w2};
                if (c393 < 3) *t[c393] = p;
                c393++;
            } break;
            case 786432: qkv_w[2] = p; break;
            case 65536:  out_w[0] = p; break;
            case 131072: out_w[1] = p; break;
            case 262144: out_w[2] = p; break;
            case 7938:   tbl[0] = p; break;
            case 15876:  tbl[1] = p; break;
            case 31752:  tbl[2] = p; break;
            default: break;
        }
    }

    bool ok = img && patch_w && patch_b && pos_emb && ln1_s && ln1_b && ln2_s &&
              ln2_b && ff_w1 && ff_b1 && ff_w2 && ff_b2;
    for (int l = 0; l < 3; l++)
        ok = ok && qkv_w[l] && out_w[l] && out_b[l] && tbl[l];
    if (!ok) {
        k_zero<<<(out_size + 255) / 256, 256>>>((float*)d_out, out_size);
        return;
    }

    const int PATCH_SMEM = (2 * 8192 + 2 * 4352) * 4;   // 100352 bytes
    cudaFuncSetAttribute(k_patch_tc,
                         cudaFuncAttributeMaxDynamicSharedMemorySize, PATCH_SMEM);

    k_permute_pw<<<(32768 * 128 + 255) / 256, 256>>>(patch_w);
    k_patch_tc<<<dim3(4, 16, 2), 256, PATCH_SMEM>>>(img);
    k_patch_sum<<<(4096 * 128 + 255) / 256, 256>>>(patch_b, pos_emb);

    const int heads[3] = {2, 4, 8};
    for (int l = 0; l < 3; l++) {
        int h = heads[l];
        int inner = 64 * h;
        int qkvld = 3 * inner;

        // ---- attention ----
        k_layernorm<<<4096, 128>>>(ln1_s + l * 512, ln1_b + l * 512);
        k_tc_nn<128><<<dim3(qkvld / 128, 32, 1), 512>>>(
            BUF_XN, 0ULL, 0ULL, 512,
            qkv_w[l], -1, 0ULL, 0ULL, 0ULL, qkvld,
            BUF_QKV, 0ULL, 0ULL, 0ULL, qkvld,
            512, 1, nullptr, 0, 0);
        k_tc_scores<<<dim3(8, 8, 4 * h), 256>>>(tbl[l], qkvld, inner, h);
        k_softmax<<<4 * h * 1024, 256>>>();
        k_tc_nn<64><<<dim3(1, 8, 4 * h), 256>>>(
            BUF_ATT, (u64)h * 1048576ULL, 1048576ULL, 1024,
            nullptr, BUF_QKV, (u64)1024 * qkvld, 64ULL,
            (u64)(2 * inner), qkvld,
            BUF_O, (u64)1024 * inner, 64ULL, 0ULL, inner,
            1024, h, nullptr, 0, 0);
        k_tc_nn<128><<<dim3(4, 32, 1), 512>>>(
            BUF_O, 0ULL, 0ULL, inner,
            out_w[l], -1, 0ULL, 0ULL, 0ULL, 512,
            BUF_X, 0ULL, 0ULL, 0ULL, 512,
            inner, 1, out_b[l], 1, 0);

        // ---- feed-forward ----
        k_layernorm<<<4096, 128>>>(ln2_s + l * 512, ln2_b + l * 512);
        k_tc_nn<128><<<dim3(2, 32, 1), 512>>>(
            BUF_XN, 0ULL, 0ULL, 512,
            ff_w1 + (size_t)l * 512 * 256, -1, 0ULL, 0ULL, 0ULL, 256,
            BUF_H, 0ULL, 0ULL, 0ULL, 256,
            512, 1, ff_b1 + l * 256, 0, 1);
        k_tc_nn<128><<<dim3(4, 32, 1), 512>>>(
            BUF_H, 0ULL, 0ULL, 256,
            ff_w2 + (size_t)l * 256 * 512, -1, 0ULL, 0ULL, 0ULL, 512,
            BUF_X, 0ULL, 0ULL, 0ULL, 512,
            256, 1, ff_b2 + l * 512, 1, 0);
    }

    k_out<<<dim3(32, 16, 4), dim3(32, 8)>>>((float*)d_out);
}